// round 5
// baseline (speedup 1.0000x reference)
#include <cuda_runtime.h>
#include <cuda_bf16.h>
#include <cuda_fp16.h>
#include <math.h>
#include <stdint.h>

#define NN 40000
#define NE 640000
#define H  128
#define ITERS 8
#define NCTA 148
#define RPC 272          // rows per CTA (multiple of 16; 147*272 + 16 = 40000)
#define PAD 136          // bf16 element stride for A and W rows

// smem element offsets (bf16 units)
#define WS_HI 0
#define WS_LO 17408                  // 128*136
#define AS_HI 34816
#define AS_LO (34816 + RPC * PAD)
#define SMEM_BYTES ((34816 + 2 * RPC * PAD) * 2)   // 217600

// ---------------- device scratch ----------------
__device__ int   g_counts[NN];
__device__ int   g_rowptr[NN + 1];
__device__ int   g_cursor[NN];
__device__ int   g_col[NE];
__device__ int   g_bsums[320];
__device__ int   g_boffs[320];
__device__ float g_xp[NN * H];
__device__ uint4 g_st0[NN * 16];     // fp16 state, 16B-aligned rows
__device__ uint4 g_st1[NN * 16];
__device__ float g_h0[NN * H];
__device__ uint4 g_wbf4[4][4352];    // per slot: [hi 128x136][lo 128x136] bf16
__device__ int   g_is64;
__device__ volatile unsigned g_gen;
__device__ unsigned g_cnt;

// ---------------- CSR build ----------------
__global__ void detect_kernel(const int* ei) {
    if (threadIdx.x == 0 && blockIdx.x == 0) {
        int any = 0;
        for (int i = 0; i < 128; i++) any |= ei[2 * i + 1];
        g_is64 = (any == 0) ? 1 : 0;
    }
}
__global__ void zero_counts_kernel() {
    int i = blockIdx.x * blockDim.x + threadIdx.x;
    if (i < NN) g_counts[i] = 0;
}
__global__ void hist_kernel(const void* __restrict__ ei) {
    int e = blockIdx.x * blockDim.x + threadIdx.x;
    if (e >= NE) return;
    int d;
    if (g_is64) d = (int)((const long long*)ei)[NE + e];
    else        d = ((const int*)ei)[NE + e];
    atomicAdd(&g_counts[d], 1);
}
__global__ void bsum_kernel() {
    int i = blockIdx.x * 128 + threadIdx.x;
    int c = (i < NN) ? g_counts[i] : 0;
    for (int o = 16; o > 0; o >>= 1) c += __shfl_down_sync(~0u, c, o);
    __shared__ int ws[4];
    if ((threadIdx.x & 31) == 0) ws[threadIdx.x >> 5] = c;
    __syncthreads();
    if (threadIdx.x == 0) g_bsums[blockIdx.x] = ws[0] + ws[1] + ws[2] + ws[3];
}
__global__ void bscan_kernel() {
    __shared__ int sm[512];
    int t = threadIdx.x;
    int v = (t < 313) ? g_bsums[t] : 0;
    sm[t] = v;
    __syncthreads();
    for (int o = 1; o < 512; o <<= 1) {
        int u = (t >= o) ? sm[t - o] : 0;
        __syncthreads();
        sm[t] += u;
        __syncthreads();
    }
    if (t < 313) g_boffs[t] = sm[t] - v;
}
__global__ void rowptr_kernel() {
    int t = threadIdx.x;
    int i = blockIdx.x * 128 + t;
    int c = (i < NN) ? g_counts[i] : 0;
    int lane = t & 31, w = t >> 5;
    int v = c;
    for (int o = 1; o < 32; o <<= 1) {
        int u = __shfl_up_sync(~0u, v, o);
        if (lane >= o) v += u;
    }
    __shared__ int ws[4], wo[4];
    if (lane == 31) ws[w] = v;
    __syncthreads();
    if (t == 0) { int s = 0; for (int j = 0; j < 4; j++) { wo[j] = s; s += ws[j]; } }
    __syncthreads();
    int excl = v - c + wo[w] + g_boffs[blockIdx.x];
    if (i < NN) { g_rowptr[i] = excl; g_cursor[i] = excl; }
    if (blockIdx.x == 0 && t == 0) g_rowptr[NN] = NE;
}
__global__ void scatter_kernel(const void* __restrict__ ei) {
    int e = blockIdx.x * blockDim.x + threadIdx.x;
    if (e >= NE) return;
    int s, d;
    if (g_is64) {
        s = (int)((const long long*)ei)[e];
        d = (int)((const long long*)ei)[NE + e];
    } else {
        s = ((const int*)ei)[e];
        d = ((const int*)ei)[NE + e];
    }
    int p = atomicAdd(&g_cursor[d], 1);
    g_col[p] = s;
}

// ---------------- weight prep ----------------
__global__ void prep_w(const float* __restrict__ w, int trans, __nv_bfloat16* __restrict__ dst) {
    int idx = blockIdx.x * blockDim.x + threadIdx.x;
    if (idx >= H * H) return;
    int n = idx >> 7, k = idx & 127;
    float a = trans ? w[k * H + n] : w[n * H + k];
    __nv_bfloat16 hi = __float2bfloat16_rn(a);
    __nv_bfloat16 lo = __float2bfloat16_rn(a - __bfloat162float(hi));
    dst[n * PAD + k] = hi;
    dst[17408 + n * PAD + k] = lo;
}

// ---------------- mma.sync helper ----------------
__device__ __forceinline__ void mma16816(float* c, const uint32_t* a, const uint32_t* b) {
    asm volatile(
        "mma.sync.aligned.m16n8k16.row.col.f32.bf16.bf16.f32 "
        "{%0,%1,%2,%3}, {%4,%5,%6,%7}, {%8,%9}, {%0,%1,%2,%3};"
        : "+f"(c[0]), "+f"(c[1]), "+f"(c[2]), "+f"(c[3])
        : "r"(a[0]), "r"(a[1]), "r"(a[2]), "r"(a[3]), "r"(b[0]), "r"(b[1]));
}

// ---------------- grid barrier (148 CTAs, 1/SM, all resident) ----------------
__device__ __forceinline__ void gbar() {
    __syncthreads();
    if (threadIdx.x == 0) {
        __threadfence();
        unsigned gen = g_gen;
        if (atomicAdd(&g_cnt, 1) == gridDim.x - 1) {
            g_cnt = 0;
            __threadfence();
            g_gen = gen + 1;
        } else {
            while (g_gen == gen) __nanosleep(32);
        }
        __threadfence();
    }
    __syncthreads();
}

// ---------------- split helpers ----------------
__device__ __forceinline__ void split4(float4 a, uint2& hv, uint2& lv) {
    __nv_bfloat16 hx = __float2bfloat16_rn(a.x), hy = __float2bfloat16_rn(a.y);
    __nv_bfloat16 hz = __float2bfloat16_rn(a.z), hw = __float2bfloat16_rn(a.w);
    __nv_bfloat16 lx = __float2bfloat16_rn(a.x - __bfloat162float(hx));
    __nv_bfloat16 ly = __float2bfloat16_rn(a.y - __bfloat162float(hy));
    __nv_bfloat16 lz = __float2bfloat16_rn(a.z - __bfloat162float(hz));
    __nv_bfloat16 lw = __float2bfloat16_rn(a.w - __bfloat162float(hw));
    __nv_bfloat162 h01(hx, hy), h23(hz, hw), l01(lx, ly), l23(lz, lw);
    hv = make_uint2(*(uint32_t*)&h01, *(uint32_t*)&h23);
    lv = make_uint2(*(uint32_t*)&l01, *(uint32_t*)&l23);
}

// ---------------- fused persistent kernel ----------------
// 16 warps: MMA layout nq = wid&3 (32-col quarter), mg = wid>>2 (m-group, stride 4).
__global__ __launch_bounds__(512, 1)
void fused_kernel(const float* __restrict__ x, float* __restrict__ out) {
    extern __shared__ __nv_bfloat16 smem[];
    const int tid  = threadIdx.x;
    const int wid  = tid >> 5, lane = tid & 31;
    const int qg   = lane & 3, rg = lane >> 2;
    const int nq   = wid & 3, mg = wid >> 2;
    const int sub  = lane >> 4, sl = lane & 15;   // gather: half-warp per node
    const int r0c  = blockIdx.x * RPC;
    const int r1c  = (r0c + RPC < NN) ? r0c + RPC : NN;
    const int rows = r1c - r0c;
    const int ntile = rows >> 4;

    const uint4* wslots = &g_wbf4[0][0];
    uint4* st[2] = { g_st0, g_st1 };
    const int* __restrict__ col = g_col;

    for (int layer = 0; layer < 2; layer++) {
        // ---- load W_in slot ----
        {
            const uint4* src = wslots + (size_t)(layer * 2) * 4352;
            uint4* d = (uint4*)smem;
#pragma unroll
            for (int i = 0; i < 9; i++) {
                int f = tid + i * 512;
                if (f < 4352) d[f] = src[f];
            }
        }
        // ---- dense A load ----
        {
            const float* srcA = layer ? g_h0 : x;
            for (int j = wid; j < rows; j += 16) {
                float4 a = *(const float4*)(srcA + (size_t)(r0c + j) * H + lane * 4);
                uint2 hv, lv;
                split4(a, hv, lv);
                int off = j * PAD + lane * 4;
                *(uint2*)(smem + AS_HI + off) = hv;
                *(uint2*)(smem + AS_LO + off) = lv;
            }
        }
        __syncthreads();

        // ---- phase MMA: xp = A @ W_in^T ; st[0] = tanh(xp) ----
        for (int t = mg; t < ntile; t += 4) {
            float acc[4][4];
#pragma unroll
            for (int nt = 0; nt < 4; nt++)
#pragma unroll
                for (int q = 0; q < 4; q++) acc[nt][q] = 0.f;
#pragma unroll
            for (int ks = 0; ks < 8; ks++) {
                const int kk = ks * 16 + qg * 2;
                const int ra = (t * 16 + rg) * PAD;
                uint32_t ah[4], al[4];
                ah[0] = *(const uint32_t*)(smem + AS_HI + ra + kk);
                ah[1] = *(const uint32_t*)(smem + AS_HI + ra + 8 * PAD + kk);
                ah[2] = *(const uint32_t*)(smem + AS_HI + ra + kk + 8);
                ah[3] = *(const uint32_t*)(smem + AS_HI + ra + 8 * PAD + kk + 8);
                al[0] = *(const uint32_t*)(smem + AS_LO + ra + kk);
                al[1] = *(const uint32_t*)(smem + AS_LO + ra + 8 * PAD + kk);
                al[2] = *(const uint32_t*)(smem + AS_LO + ra + kk + 8);
                al[3] = *(const uint32_t*)(smem + AS_LO + ra + 8 * PAD + kk + 8);
#pragma unroll
                for (int nt = 0; nt < 4; nt++) {
                    const int n = nq * 32 + nt * 8 + rg;
                    uint32_t bh[2], bl[2];
                    bh[0] = *(const uint32_t*)(smem + WS_HI + n * PAD + kk);
                    bh[1] = *(const uint32_t*)(smem + WS_HI + n * PAD + kk + 8);
                    bl[0] = *(const uint32_t*)(smem + WS_LO + n * PAD + kk);
                    bl[1] = *(const uint32_t*)(smem + WS_LO + n * PAD + kk + 8);
                    mma16816(acc[nt], ah, bh);
                    mma16816(acc[nt], ah, bl);
                    mma16816(acc[nt], al, bh);
                }
            }
#pragma unroll
            for (int half = 0; half < 2; half++) {
                const int row = r0c + t * 16 + rg + half * 8;
#pragma unroll
                for (int nt = 0; nt < 4; nt++) {
                    const int colj = nq * 32 + nt * 8 + qg * 2;
                    float2 o = make_float2(acc[nt][half * 2], acc[nt][half * 2 + 1]);
                    *(float2*)(g_xp + (size_t)row * H + colj) = o;
                    __half2 p = __floats2half2_rn(tanhf(o.x), tanhf(o.y));
                    *(__half2*)((__half*)st[0] + (size_t)row * H + colj) = p;
                }
            }
        }
        gbar();

        // ---- load W_rec slot ----
        {
            const uint4* src = wslots + (size_t)(layer * 2 + 1) * 4352;
            uint4* d = (uint4*)smem;
#pragma unroll
            for (int i = 0; i < 9; i++) {
                int f = tid + i * 512;
                if (f < 4352) d[f] = src[f];
            }
        }

        for (int it = 0; it < ITERS; it++) {
            // ---- gather: 2 nodes/warp, 16 lanes x uint4, unroll 4 ----
            const uint4* __restrict__ rd = st[it & 1];
            for (int jj = wid; jj * 2 < rows; jj += 16) {
                const int j = jj * 2 + sub;
                const int node = r0c + j;
                const int beg = g_rowptr[node], end = g_rowptr[node + 1];
                float a0 = 0.f, a1 = 0.f, a2 = 0.f, a3 = 0.f;
                float a4 = 0.f, a5 = 0.f, a6 = 0.f, a7 = 0.f;
                for (int p = beg; p < end; p += 4) {
#pragma unroll
                    for (int u = 0; u < 4; u++) {
                        int pe = p + u;
                        bool ok = pe < end;
                        int idx = col[ok ? pe : beg];
                        uint4 v = __ldg(&rd[(size_t)idx * 16 + sl]);
                        if (ok) {
                            float2 f0 = __half22float2(*(const __half2*)&v.x);
                            float2 f1 = __half22float2(*(const __half2*)&v.y);
                            float2 f2 = __half22float2(*(const __half2*)&v.z);
                            float2 f3 = __half22float2(*(const __half2*)&v.w);
                            a0 += f0.x; a1 += f0.y; a2 += f1.x; a3 += f1.y;
                            a4 += f2.x; a5 += f2.y; a6 += f3.x; a7 += f3.y;
                        }
                    }
                }
                uint2 h0v, l0v, h1v, l1v;
                split4(make_float4(a0, a1, a2, a3), h0v, l0v);
                split4(make_float4(a4, a5, a6, a7), h1v, l1v);
                int off = j * PAD + sl * 8;
                *(uint4*)(smem + AS_HI + off) = make_uint4(h0v.x, h0v.y, h1v.x, h1v.y);
                *(uint4*)(smem + AS_LO + off) = make_uint4(l0v.x, l0v.y, l1v.x, l1v.y);
            }
            __syncthreads();

            // ---- MMA + fused epilogue ----
            const bool last = (it == ITERS - 1);
            for (int t = mg; t < ntile; t += 4) {
                float acc[4][4];
#pragma unroll
                for (int nt = 0; nt < 4; nt++)
#pragma unroll
                    for (int q = 0; q < 4; q++) acc[nt][q] = 0.f;
#pragma unroll
                for (int ks = 0; ks < 8; ks++) {
                    const int kk = ks * 16 + qg * 2;
                    const int ra = (t * 16 + rg) * PAD;
                    uint32_t ah[4], al[4];
                    ah[0] = *(const uint32_t*)(smem + AS_HI + ra + kk);
                    ah[1] = *(const uint32_t*)(smem + AS_HI + ra + 8 * PAD + kk);
                    ah[2] = *(const uint32_t*)(smem + AS_HI + ra + kk + 8);
                    ah[3] = *(const uint32_t*)(smem + AS_HI + ra + 8 * PAD + kk + 8);
                    al[0] = *(const uint32_t*)(smem + AS_LO + ra + kk);
                    al[1] = *(const uint32_t*)(smem + AS_LO + ra + 8 * PAD + kk);
                    al[2] = *(const uint32_t*)(smem + AS_LO + ra + kk + 8);
                    al[3] = *(const uint32_t*)(smem + AS_LO + ra + 8 * PAD + kk + 8);
#pragma unroll
                    for (int nt = 0; nt < 4; nt++) {
                        const int n = nq * 32 + nt * 8 + rg;
                        uint32_t bh[2], bl[2];
                        bh[0] = *(const uint32_t*)(smem + WS_HI + n * PAD + kk);
                        bh[1] = *(const uint32_t*)(smem + WS_HI + n * PAD + kk + 8);
                        bl[0] = *(const uint32_t*)(smem + WS_LO + n * PAD + kk);
                        bl[1] = *(const uint32_t*)(smem + WS_LO + n * PAD + kk + 8);
                        mma16816(acc[nt], ah, bh);
                        mma16816(acc[nt], ah, bl);
                        mma16816(acc[nt], al, bh);
                    }
                }
#pragma unroll
                for (int half = 0; half < 2; half++) {
                    const int row = r0c + t * 16 + rg + half * 8;
#pragma unroll
                    for (int nt = 0; nt < 4; nt++) {
                        const int colj = nq * 32 + nt * 8 + qg * 2;
                        float2 xv = *(const float2*)(g_xp + (size_t)row * H + colj);
                        float2 o = make_float2(tanhf(acc[nt][half * 2] + xv.x),
                                               tanhf(acc[nt][half * 2 + 1] + xv.y));
                        if (!last) {
                            __half2 p = __floats2half2_rn(o.x, o.y);
                            *(__half2*)((__half*)st[(it + 1) & 1] + (size_t)row * H + colj) = p;
                        } else if (layer == 0) {
                            *(float2*)(g_h0 + (size_t)row * H + colj) = o;
                        } else {
                            *(float2*)(out + (size_t)row * H + colj) = o;
                        }
                    }
                }
            }
            gbar();
        }
    }
}

// ---------------- launcher ----------------
extern "C" void kernel_launch(void* const* d_in, const int* in_sizes, int n_in,
                              void* d_out, int out_size) {
    const void*  ei     = d_in[0];
    const float* x      = (const float*)d_in[1];
    const float* w_in0  = (const float*)d_in[2];
    const float* w_rec0 = (const float*)d_in[3];
    const float* w_in1  = (const float*)d_in[4];
    const float* w_rec1 = (const float*)d_in[5];
    float*       out    = (float*)d_out;

    void* pwb;
    cudaGetSymbolAddress(&pwb, g_wbf4);
    __nv_bfloat16* wbf = (__nv_bfloat16*)pwb;

    cudaFuncSetAttribute(fused_kernel, cudaFuncAttributeMaxDynamicSharedMemorySize, SMEM_BYTES);

    const int GB = (NN + 127) / 128;
    detect_kernel<<<1, 32>>>((const int*)ei);
    zero_counts_kernel<<<(NN + 255) / 256, 256>>>();
    hist_kernel<<<(NE + 255) / 256, 256>>>(ei);
    bsum_kernel<<<GB, 128>>>();
    bscan_kernel<<<1, 512>>>();
    rowptr_kernel<<<GB, 128>>>();
    scatter_kernel<<<(NE + 255) / 256, 256>>>(ei);

    prep_w<<<64, 256>>>(w_in0,  0, wbf + 0 * 34816);
    prep_w<<<64, 256>>>(w_rec0, 1, wbf + 1 * 34816);
    prep_w<<<64, 256>>>(w_in1,  0, wbf + 2 * 34816);
    prep_w<<<64, 256>>>(w_rec1, 1, wbf + 3 * 34816);

    fused_kernel<<<NCTA, 512, SMEM_BYTES>>>(x, out);
}

// round 6
// speedup vs baseline: 1.4673x; 1.4673x over previous
#include <cuda_runtime.h>
#include <cuda_bf16.h>
#include <cuda_fp16.h>
#include <math.h>
#include <stdint.h>

#define NN 40000
#define NE 640000
#define H  128
#define ITERS 8

// GEMM smem byte offsets
#define WHI_B 0
#define WLO_B 34816
#define AHI_B 69632
#define ALO_B 88064
#define SMEM_GEMM 106496     // <= 113KB -> 2 CTAs/SM

// ---------------- device scratch ----------------
__device__ int   g_counts[NN];
__device__ int   g_rowptr[NN + 1];
__device__ int   g_cursor[NN];
__device__ int   g_col[NE];
__device__ int   g_bsums[320];
__device__ int   g_boffs[320];
__device__ float g_xp[NN * H];
__device__ uint2 g_st0[NN * 32];     // fp16 state (128 half / row)
__device__ uint2 g_st1[NN * 32];
__device__ uint2 g_agH[NN * 32];     // aggr bf16 hi  (128 bf16 / row)
__device__ uint2 g_agL[NN * 32];     // aggr bf16 lo
__device__ uint2 g_dh[NN * 32];      // dense-A bf16 hi (x, then h0)
__device__ uint2 g_dl[NN * 32];
__device__ uint4 g_wpad[4 * 4352];   // per slot: [hi 128x136][lo 128x136] bf16
__device__ int   g_is64;

// ---------------- PTX helpers ----------------
__device__ __forceinline__ uint32_t smem_u32(const void* p) {
    uint32_t a;
    asm("{ .reg .u64 t; cvta.to.shared.u64 t, %1; cvt.u32.u64 %0, t; }" : "=r"(a) : "l"(p));
    return a;
}
__device__ __forceinline__ void cpa16(uint32_t dst, const void* src) {
    asm volatile("cp.async.cg.shared.global [%0], [%1], 16;" :: "r"(dst), "l"(src));
}
__device__ __forceinline__ void cpa_commit() { asm volatile("cp.async.commit_group;"); }
__device__ __forceinline__ void cpa_wait0()  { asm volatile("cp.async.wait_group 0;"); }
__device__ __forceinline__ void ldsm4(uint32_t* r, uint32_t addr) {
    asm volatile("ldmatrix.sync.aligned.m8n8.x4.shared.b16 {%0,%1,%2,%3}, [%4];"
        : "=r"(r[0]), "=r"(r[1]), "=r"(r[2]), "=r"(r[3]) : "r"(addr));
}
__device__ __forceinline__ void mma16816(float* c, const uint32_t* a, const uint32_t* b) {
    asm volatile(
        "mma.sync.aligned.m16n8k16.row.col.f32.bf16.bf16.f32 "
        "{%0,%1,%2,%3}, {%4,%5,%6,%7}, {%8,%9}, {%0,%1,%2,%3};"
        : "+f"(c[0]), "+f"(c[1]), "+f"(c[2]), "+f"(c[3])
        : "r"(a[0]), "r"(a[1]), "r"(a[2]), "r"(a[3]), "r"(b[0]), "r"(b[1]));
}
__device__ __forceinline__ void split4(float4 a, uint2& hv, uint2& lv) {
    __nv_bfloat16 hx = __float2bfloat16_rn(a.x), hy = __float2bfloat16_rn(a.y);
    __nv_bfloat16 hz = __float2bfloat16_rn(a.z), hw = __float2bfloat16_rn(a.w);
    __nv_bfloat16 lx = __float2bfloat16_rn(a.x - __bfloat162float(hx));
    __nv_bfloat16 ly = __float2bfloat16_rn(a.y - __bfloat162float(hy));
    __nv_bfloat16 lz = __float2bfloat16_rn(a.z - __bfloat162float(hz));
    __nv_bfloat16 lw = __float2bfloat16_rn(a.w - __bfloat162float(hw));
    __nv_bfloat162 h01(hx, hy), h23(hz, hw), l01(lx, ly), l23(lz, lw);
    hv = make_uint2(*(uint32_t*)&h01, *(uint32_t*)&h23);
    lv = make_uint2(*(uint32_t*)&l01, *(uint32_t*)&l23);
}

// ---------------- CSR build ----------------
__global__ void detect_kernel(const int* ei) {
    if (threadIdx.x == 0 && blockIdx.x == 0) {
        int any = 0;
        for (int i = 0; i < 128; i++) any |= ei[2 * i + 1];
        g_is64 = (any == 0) ? 1 : 0;
    }
}
__global__ void zero_counts_kernel() {
    int i = blockIdx.x * blockDim.x + threadIdx.x;
    if (i < NN) g_counts[i] = 0;
}
__global__ void hist_kernel(const void* __restrict__ ei) {
    int e = blockIdx.x * blockDim.x + threadIdx.x;
    if (e >= NE) return;
    int d;
    if (g_is64) d = (int)((const long long*)ei)[NE + e];
    else        d = ((const int*)ei)[NE + e];
    atomicAdd(&g_counts[d], 1);
}
__global__ void bsum_kernel() {
    int i = blockIdx.x * 128 + threadIdx.x;
    int c = (i < NN) ? g_counts[i] : 0;
    for (int o = 16; o > 0; o >>= 1) c += __shfl_down_sync(~0u, c, o);
    __shared__ int ws[4];
    if ((threadIdx.x & 31) == 0) ws[threadIdx.x >> 5] = c;
    __syncthreads();
    if (threadIdx.x == 0) g_bsums[blockIdx.x] = ws[0] + ws[1] + ws[2] + ws[3];
}
__global__ void bscan_kernel() {
    __shared__ int sm[512];
    int t = threadIdx.x;
    int v = (t < 313) ? g_bsums[t] : 0;
    sm[t] = v;
    __syncthreads();
    for (int o = 1; o < 512; o <<= 1) {
        int u = (t >= o) ? sm[t - o] : 0;
        __syncthreads();
        sm[t] += u;
        __syncthreads();
    }
    if (t < 313) g_boffs[t] = sm[t] - v;
}
__global__ void rowptr_kernel() {
    int t = threadIdx.x;
    int i = blockIdx.x * 128 + t;
    int c = (i < NN) ? g_counts[i] : 0;
    int lane = t & 31, w = t >> 5;
    int v = c;
    for (int o = 1; o < 32; o <<= 1) {
        int u = __shfl_up_sync(~0u, v, o);
        if (lane >= o) v += u;
    }
    __shared__ int ws[4], wo[4];
    if (lane == 31) ws[w] = v;
    __syncthreads();
    if (t == 0) { int s = 0; for (int j = 0; j < 4; j++) { wo[j] = s; s += ws[j]; } }
    __syncthreads();
    int excl = v - c + wo[w] + g_boffs[blockIdx.x];
    if (i < NN) { g_rowptr[i] = excl; g_cursor[i] = excl; }
    if (blockIdx.x == 0 && t == 0) g_rowptr[NN] = NE;
}
__global__ void scatter_kernel(const void* __restrict__ ei) {
    int e = blockIdx.x * blockDim.x + threadIdx.x;
    if (e >= NE) return;
    int s, d;
    if (g_is64) {
        s = (int)((const long long*)ei)[e];
        d = (int)((const long long*)ei)[NE + e];
    } else {
        s = ((const int*)ei)[e];
        d = ((const int*)ei)[NE + e];
    }
    int p = atomicAdd(&g_cursor[d], 1);
    g_col[p] = s;
}

// ---------------- weight prep: all 4 slots, bf16 hi/lo [n][k] pad 136 -----------
__global__ void prep_w_all(const float* __restrict__ w0, const float* __restrict__ w1,
                           const float* __restrict__ w2, const float* __restrict__ w3) {
    int slot = blockIdx.x >> 6;
    int idx  = (blockIdx.x & 63) * 256 + threadIdx.x;
    if (idx >= H * H) return;
    const float* w = (slot == 0) ? w0 : (slot == 1) ? w1 : (slot == 2) ? w2 : w3;
    int trans = slot & 1;   // w_rec slots need W^T
    int n = idx >> 7, k = idx & 127;
    float a = trans ? w[k * H + n] : w[n * H + k];
    __nv_bfloat16 hi = __float2bfloat16_rn(a);
    __nv_bfloat16 lo = __float2bfloat16_rn(a - __bfloat162float(hi));
    __nv_bfloat16* dst = (__nv_bfloat16*)(g_wpad + (size_t)slot * 4352);
    dst[n * 136 + k] = hi;
    dst[17408 + n * 136 + k] = lo;
}

// ---------------- split x into bf16 hi/lo ----------------
__global__ void split_x_kernel(const float4* __restrict__ src) {
    int i = blockIdx.x * blockDim.x + threadIdx.x;
    if (i >= NN * 32) return;
    uint2 hv, lv;
    split4(src[i], hv, lv);
    g_dh[i] = hv;
    g_dl[i] = lv;
}

// ---------------- CSR gather: fp16 state -> bf16 hi/lo aggr ----------------
__global__ __launch_bounds__(256) void gather_kernel(const uint2* __restrict__ st,
                                                     uint2* __restrict__ aH,
                                                     uint2* __restrict__ aL) {
    int w    = (blockIdx.x * blockDim.x + threadIdx.x) >> 5;
    int lane = threadIdx.x & 31;
    if (w >= NN) return;
    int beg = g_rowptr[w], end = g_rowptr[w + 1];
    float4 acc = make_float4(0.f, 0.f, 0.f, 0.f);
    int p = beg;
    for (; p + 1 < end; p += 2) {
        int s0 = g_col[p], s1 = g_col[p + 1];
        uint2 v0 = __ldg(&st[(size_t)s0 * 32 + lane]);
        uint2 v1 = __ldg(&st[(size_t)s1 * 32 + lane]);
        float2 a0 = __half22float2(*(const __half2*)&v0.x);
        float2 b0 = __half22float2(*(const __half2*)&v0.y);
        float2 a1 = __half22float2(*(const __half2*)&v1.x);
        float2 b1 = __half22float2(*(const __half2*)&v1.y);
        acc.x += a0.x + a1.x; acc.y += a0.y + a1.y;
        acc.z += b0.x + b1.x; acc.w += b0.y + b1.y;
    }
    if (p < end) {
        int s0 = g_col[p];
        uint2 v0 = __ldg(&st[(size_t)s0 * 32 + lane]);
        float2 a0 = __half22float2(*(const __half2*)&v0.x);
        float2 b0 = __half22float2(*(const __half2*)&v0.y);
        acc.x += a0.x; acc.y += a0.y; acc.z += b0.x; acc.w += b0.y;
    }
    uint2 hv, lv;
    split4(acc, hv, lv);
    aH[(size_t)w * 32 + lane] = hv;
    aL[(size_t)w * 32 + lane] = lv;
}

// ---------------- tensor GEMM via ldmatrix + cp.async ----------------
// C[m][n] = post( A @ W^T [+ XP] ), A pre-split bf16 hi/lo (row stride 128).
// MODE 0: write xp fp32 + st0 = tanh (no ADD)
// MODE 1: ADD xp, tanh, write fp16 state
// MODE 2: ADD xp, tanh, write bf16 split (h0)
// MODE 3: ADD xp, tanh, write fp32 out
template <int MODE>
__global__ __launch_bounds__(256, 2)
void gemm_k(const uint4* __restrict__ Ah, const uint4* __restrict__ Al,
            const uint4* __restrict__ W4, const float* __restrict__ XP,
            float* __restrict__ xpOut, void* __restrict__ dstOut,
            uint32_t* __restrict__ dhOut, uint32_t* __restrict__ dlOut) {
    extern __shared__ char smc[];
    const uint32_t sb = smem_u32(smc);
    const int tid = threadIdx.x, wid = tid >> 5, lane = tid & 31;
    const int qg = lane & 3, rg = lane >> 2;
    const int nq = wid & 1, mg = wid >> 1;
    const int rowBase = blockIdx.x * 128;

    // prologue: cp.async W (4352 x 16B) + A chunk 0
#pragma unroll
    for (int i = 0; i < 17; i++) {
        int f = tid + i * 256;
        cpa16(sb + f * 16, W4 + f);
    }
#pragma unroll
    for (int i = 0; i < 4; i++) {
        int f = tid + i * 256;
        int r = f >> 3, u = f & 7;
        int srow = rowBase + r; if (srow >= NN) srow = 0;
        cpa16(sb + AHI_B + r * 144 + u * 16, Ah + (size_t)srow * 16 + u);
        cpa16(sb + ALO_B + r * 144 + u * 16, Al + (size_t)srow * 16 + u);
    }
    cpa_commit();

    // fragment addresses
    const int lrow = lane & 15, khalf = lane >> 4;
    const uint32_t aoff0 = (mg * 16 + lrow) * 144 + khalf * 16;
    const uint32_t aoff1 = ((mg + 4) * 16 + lrow) * 144 + khalf * 16;
    const int og = lane >> 3, lr = lane & 7;
    const uint32_t boff = (uint32_t)(nq * 64 + (og >> 1) * 8 + lr) * 272 + (og & 1) * 16;

    float acc[2][8][4];
#pragma unroll
    for (int m = 0; m < 2; m++)
#pragma unroll
        for (int nt = 0; nt < 8; nt++)
#pragma unroll
            for (int q = 0; q < 4; q++) acc[m][nt][q] = 0.f;

    for (int c = 0; c < 2; c++) {
        cpa_wait0();
        __syncthreads();
#pragma unroll
        for (int ks = 0; ks < 4; ks++) {
            const uint32_t kb = ks * 32;
            uint32_t ah0[4], ah1[4], al0[4], al1[4];
            ldsm4(ah0, sb + AHI_B + aoff0 + kb);
            ldsm4(ah1, sb + AHI_B + aoff1 + kb);
            ldsm4(al0, sb + ALO_B + aoff0 + kb);
            ldsm4(al1, sb + ALO_B + aoff1 + kb);
            const uint32_t kwb = c * 128 + kb;
#pragma unroll
            for (int p = 0; p < 4; p++) {
                uint32_t bh[4], bl[4];
                ldsm4(bh, sb + WHI_B + boff + p * 4352 + kwb);
                ldsm4(bl, sb + WLO_B + boff + p * 4352 + kwb);
                mma16816(acc[0][2 * p],     ah0, &bh[0]);
                mma16816(acc[0][2 * p],     ah0, &bl[0]);
                mma16816(acc[0][2 * p],     al0, &bh[0]);
                mma16816(acc[0][2 * p + 1], ah0, &bh[2]);
                mma16816(acc[0][2 * p + 1], ah0, &bl[2]);
                mma16816(acc[0][2 * p + 1], al0, &bh[2]);
                mma16816(acc[1][2 * p],     ah1, &bh[0]);
                mma16816(acc[1][2 * p],     ah1, &bl[0]);
                mma16816(acc[1][2 * p],     al1, &bh[0]);
                mma16816(acc[1][2 * p + 1], ah1, &bh[2]);
                mma16816(acc[1][2 * p + 1], ah1, &bl[2]);
                mma16816(acc[1][2 * p + 1], al1, &bh[2]);
            }
        }
        if (c == 0) {
            __syncthreads();
#pragma unroll
            for (int i = 0; i < 4; i++) {
                int f = tid + i * 256;
                int r = f >> 3, u = f & 7;
                int srow = rowBase + r; if (srow >= NN) srow = 0;
                cpa16(sb + AHI_B + r * 144 + u * 16, Ah + (size_t)srow * 16 + 8 + u);
                cpa16(sb + ALO_B + r * 144 + u * 16, Al + (size_t)srow * 16 + 8 + u);
            }
            cpa_commit();
        }
    }

    // epilogue
#pragma unroll
    for (int m = 0; m < 2; m++) {
        const int t = mg + m * 4;
#pragma unroll
        for (int half = 0; half < 2; half++) {
            const int row = rowBase + t * 16 + rg + half * 8;
            if (row >= NN) continue;
#pragma unroll
            for (int nt = 0; nt < 8; nt++) {
                const int col = nq * 64 + nt * 8 + qg * 2;
                float ox = acc[m][nt][half * 2], oy = acc[m][nt][half * 2 + 1];
                if (MODE != 0) {
                    float2 xv = *(const float2*)(XP + (size_t)row * H + col);
                    ox += xv.x; oy += xv.y;
                }
                if (MODE == 0) {
                    *(float2*)(xpOut + (size_t)row * H + col) = make_float2(ox, oy);
                    __half2 pp = __floats2half2_rn(tanhf(ox), tanhf(oy));
                    *(__half2*)((__half*)dstOut + (size_t)row * H + col) = pp;
                } else if (MODE == 1) {
                    __half2 pp = __floats2half2_rn(tanhf(ox), tanhf(oy));
                    *(__half2*)((__half*)dstOut + (size_t)row * H + col) = pp;
                } else if (MODE == 2) {
                    ox = tanhf(ox); oy = tanhf(oy);
                    __nv_bfloat16 hx = __float2bfloat16_rn(ox), hy = __float2bfloat16_rn(oy);
                    __nv_bfloat16 lx = __float2bfloat16_rn(ox - __bfloat162float(hx));
                    __nv_bfloat16 ly = __float2bfloat16_rn(oy - __bfloat162float(hy));
                    __nv_bfloat162 hp(hx, hy), lp(lx, ly);
                    dhOut[(size_t)row * 64 + (col >> 1)] = *(uint32_t*)&hp;
                    dlOut[(size_t)row * 64 + (col >> 1)] = *(uint32_t*)&lp;
                } else {
                    *(float2*)((float*)dstOut + (size_t)row * H + col) =
                        make_float2(tanhf(ox), tanhf(oy));
                }
            }
        }
    }
}

// ---------------- launcher ----------------
extern "C" void kernel_launch(void* const* d_in, const int* in_sizes, int n_in,
                              void* d_out, int out_size) {
    const void*  ei     = d_in[0];
    const float* x      = (const float*)d_in[1];
    const float* w_in0  = (const float*)d_in[2];
    const float* w_rec0 = (const float*)d_in[3];
    const float* w_in1  = (const float*)d_in[4];
    const float* w_rec1 = (const float*)d_in[5];
    float*       out    = (float*)d_out;

    void *pxp, *ps0, *ps1, *pah, *pal, *pdh, *pdl, *pwp;
    cudaGetSymbolAddress(&pxp, g_xp);
    cudaGetSymbolAddress(&ps0, g_st0);
    cudaGetSymbolAddress(&ps1, g_st1);
    cudaGetSymbolAddress(&pah, g_agH);
    cudaGetSymbolAddress(&pal, g_agL);
    cudaGetSymbolAddress(&pdh, g_dh);
    cudaGetSymbolAddress(&pdl, g_dl);
    cudaGetSymbolAddress(&pwp, g_wpad);
    float* xp   = (float*)pxp;
    uint2* st[2] = { (uint2*)ps0, (uint2*)ps1 };
    uint2* agH  = (uint2*)pah;
    uint2* agL  = (uint2*)pal;
    uint2* dh   = (uint2*)pdh;
    uint2* dl   = (uint2*)pdl;
    uint4* wp   = (uint4*)pwp;

    cudaFuncSetAttribute(gemm_k<0>, cudaFuncAttributeMaxDynamicSharedMemorySize, SMEM_GEMM);
    cudaFuncSetAttribute(gemm_k<1>, cudaFuncAttributeMaxDynamicSharedMemorySize, SMEM_GEMM);
    cudaFuncSetAttribute(gemm_k<2>, cudaFuncAttributeMaxDynamicSharedMemorySize, SMEM_GEMM);
    cudaFuncSetAttribute(gemm_k<3>, cudaFuncAttributeMaxDynamicSharedMemorySize, SMEM_GEMM);

    const int GB = (NN + 127) / 128;   // 313

    // ---- CSR build ----
    detect_kernel<<<1, 32>>>((const int*)ei);
    zero_counts_kernel<<<(NN + 255) / 256, 256>>>();
    hist_kernel<<<(NE + 255) / 256, 256>>>(ei);
    bsum_kernel<<<GB, 128>>>();
    bscan_kernel<<<1, 512>>>();
    rowptr_kernel<<<GB, 128>>>();
    scatter_kernel<<<(NE + 255) / 256, 256>>>(ei);

    // ---- weight prep + x split ----
    prep_w_all<<<256, 256>>>(w_in0, w_rec0, w_in1, w_rec1);
    split_x_kernel<<<(NN * 32 + 255) / 256, 256>>>((const float4*)x);

    // ---- layer 0 ----
    gemm_k<0><<<GB, 256, SMEM_GEMM>>>((const uint4*)dh, (const uint4*)dl, wp + 0 * 4352,
                                      nullptr, xp, st[0], nullptr, nullptr);
    for (int it = 0; it < ITERS; it++) {
        gather_kernel<<<(NN * 32 + 255) / 256, 256>>>(st[it & 1], agH, agL);
        if (it < ITERS - 1)
            gemm_k<1><<<GB, 256, SMEM_GEMM>>>((const uint4*)agH, (const uint4*)agL, wp + 1 * 4352,
                                              xp, nullptr, st[(it + 1) & 1], nullptr, nullptr);
        else
            gemm_k<2><<<GB, 256, SMEM_GEMM>>>((const uint4*)agH, (const uint4*)agL, wp + 1 * 4352,
                                              xp, nullptr, nullptr, (uint32_t*)dh, (uint32_t*)dl);
    }

    // ---- layer 1 ----
    gemm_k<0><<<GB, 256, SMEM_GEMM>>>((const uint4*)dh, (const uint4*)dl, wp + 2 * 4352,
                                      nullptr, xp, st[0], nullptr, nullptr);
    for (int it = 0; it < ITERS; it++) {
        gather_kernel<<<(NN * 32 + 255) / 256, 256>>>(st[it & 1], agH, agL);
        if (it < ITERS - 1)
            gemm_k<1><<<GB, 256, SMEM_GEMM>>>((const uint4*)agH, (const uint4*)agL, wp + 3 * 4352,
                                              xp, nullptr, st[(it + 1) & 1], nullptr, nullptr);
        else
            gemm_k<3><<<GB, 256, SMEM_GEMM>>>((const uint4*)agH, (const uint4*)agL, wp + 3 * 4352,
                                              xp, nullptr, out, nullptr, nullptr);
    }
}

// round 7
// speedup vs baseline: 1.5861x; 1.0809x over previous
#include <cuda_runtime.h>
#include <cuda_fp16.h>
#include <math.h>
#include <stdint.h>

#define NN 40000
#define NE 640000
#define H  128
#define ITERS 8

// GEMM smem byte offsets
#define WHI_B 0
#define WLO_B 34816
#define A_B   69632
#define SMEM_GEMM 88064      // 2 CTAs/SM

// ---------------- device scratch ----------------
__device__ int   g_counts[NN];
__device__ int   g_rowptr[NN + 1];
__device__ int   g_cursor[NN];
__device__ int   g_col[NE];
__device__ int   g_bsums[320];
__device__ int   g_boffs[320];
__device__ float g_xp[NN * H];
__device__ uint2 g_st0[NN * 32];     // fp16 state
__device__ uint2 g_st1[NN * 32];
__device__ uint2 g_ag[NN * 32];      // fp16 aggr (single)
__device__ uint2 g_dx[NN * 32];      // fp16 dense input (x)
__device__ uint2 g_dh[NN * 32];      // fp16 dense input (h0)
__device__ uint4 g_wp[4 * 4352];     // per slot: [hi 128x136][lo 128x136] fp16
__device__ int   g_is64;

// ---------------- PTX helpers ----------------
__device__ __forceinline__ uint32_t smem_u32(const void* p) {
    uint32_t a;
    asm("{ .reg .u64 t; cvta.to.shared.u64 t, %1; cvt.u32.u64 %0, t; }" : "=r"(a) : "l"(p));
    return a;
}
__device__ __forceinline__ void cpa16(uint32_t dst, const void* src) {
    asm volatile("cp.async.cg.shared.global [%0], [%1], 16;" :: "r"(dst), "l"(src));
}
__device__ __forceinline__ void cpa_commit() { asm volatile("cp.async.commit_group;"); }
__device__ __forceinline__ void cpa_wait0()  { asm volatile("cp.async.wait_group 0;"); }
__device__ __forceinline__ void ldsm4(uint32_t* r, uint32_t addr) {
    asm volatile("ldmatrix.sync.aligned.m8n8.x4.shared.b16 {%0,%1,%2,%3}, [%4];"
        : "=r"(r[0]), "=r"(r[1]), "=r"(r[2]), "=r"(r[3]) : "r"(addr));
}
__device__ __forceinline__ void mma16816(float* c, const uint32_t* a, const uint32_t* b) {
    asm volatile(
        "mma.sync.aligned.m16n8k16.row.col.f32.f16.f16.f32 "
        "{%0,%1,%2,%3}, {%4,%5,%6,%7}, {%8,%9}, {%0,%1,%2,%3};"
        : "+f"(c[0]), "+f"(c[1]), "+f"(c[2]), "+f"(c[3])
        : "r"(a[0]), "r"(a[1]), "r"(a[2]), "r"(a[3]), "r"(b[0]), "r"(b[1]));
}

// ---------------- CSR build ----------------
__global__ void zero_detect_kernel(const int* ei) {
    int i = blockIdx.x * blockDim.x + threadIdx.x;
    if (i < NN) g_counts[i] = 0;
    if (i == 0) {
        int any = 0;
        for (int k = 0; k < 128; k++) any |= ei[2 * k + 1];
        g_is64 = (any == 0) ? 1 : 0;
    }
}
__global__ void hist_kernel(const void* __restrict__ ei) {
    int e = blockIdx.x * blockDim.x + threadIdx.x;
    if (e >= NE) return;
    int d;
    if (g_is64) d = (int)((const long long*)ei)[NE + e];
    else        d = ((const int*)ei)[NE + e];
    atomicAdd(&g_counts[d], 1);
}
__global__ void bsum_kernel() {
    int i = blockIdx.x * 128 + threadIdx.x;
    int c = (i < NN) ? g_counts[i] : 0;
    for (int o = 16; o > 0; o >>= 1) c += __shfl_down_sync(~0u, c, o);
    __shared__ int ws[4];
    if ((threadIdx.x & 31) == 0) ws[threadIdx.x >> 5] = c;
    __syncthreads();
    if (threadIdx.x == 0) g_bsums[blockIdx.x] = ws[0] + ws[1] + ws[2] + ws[3];
}
__global__ void bscan_kernel() {
    __shared__ int sm[512];
    int t = threadIdx.x;
    int v = (t < 313) ? g_bsums[t] : 0;
    sm[t] = v;
    __syncthreads();
    for (int o = 1; o < 512; o <<= 1) {
        int u = (t >= o) ? sm[t - o] : 0;
        __syncthreads();
        sm[t] += u;
        __syncthreads();
    }
    if (t < 313) g_boffs[t] = sm[t] - v;
}
__global__ void rowptr_kernel() {
    int t = threadIdx.x;
    int i = blockIdx.x * 128 + t;
    int c = (i < NN) ? g_counts[i] : 0;
    int lane = t & 31, w = t >> 5;
    int v = c;
    for (int o = 1; o < 32; o <<= 1) {
        int u = __shfl_up_sync(~0u, v, o);
        if (lane >= o) v += u;
    }
    __shared__ int ws[4], wo[4];
    if (lane == 31) ws[w] = v;
    __syncthreads();
    if (t == 0) { int s = 0; for (int j = 0; j < 4; j++) { wo[j] = s; s += ws[j]; } }
    __syncthreads();
    int excl = v - c + wo[w] + g_boffs[blockIdx.x];
    if (i < NN) { g_rowptr[i] = excl; g_cursor[i] = excl; }
    if (blockIdx.x == 0 && t == 0) g_rowptr[NN] = NE;
}
__global__ void scatter_kernel(const void* __restrict__ ei) {
    int e = blockIdx.x * blockDim.x + threadIdx.x;
    if (e >= NE) return;
    int s, d;
    if (g_is64) {
        s = (int)((const long long*)ei)[e];
        d = (int)((const long long*)ei)[NE + e];
    } else {
        s = ((const int*)ei)[e];
        d = ((const int*)ei)[NE + e];
    }
    int p = atomicAdd(&g_cursor[d], 1);
    g_col[p] = s;
}

// ---------------- weight prep: fp32 -> fp16 hi/lo, [n][k] pad 136 ----------------
__global__ void prep_w_all(const float* __restrict__ w0, const float* __restrict__ w1,
                           const float* __restrict__ w2, const float* __restrict__ w3) {
    int slot = blockIdx.x >> 6;
    int idx  = (blockIdx.x & 63) * 256 + threadIdx.x;
    if (idx >= H * H) return;
    const float* w = (slot == 0) ? w0 : (slot == 1) ? w1 : (slot == 2) ? w2 : w3;
    int trans = slot & 1;   // w_rec slots need W^T
    int n = idx >> 7, k = idx & 127;
    float a = trans ? w[k * H + n] : w[n * H + k];
    __half hi = __float2half_rn(a);
    __half lo = __float2half_rn(a - __half2float(hi));
    __half* dst = (__half*)(g_wp + (size_t)slot * 4352);
    dst[n * 136 + k] = hi;
    dst[17408 + n * 136 + k] = lo;
}

// ---------------- split x -> fp16 ----------------
__global__ void split_x_kernel(const float4* __restrict__ src) {
    int i = blockIdx.x * blockDim.x + threadIdx.x;
    if (i >= NN * 32) return;
    float4 v = src[i];
    __half2 a = __floats2half2_rn(v.x, v.y);
    __half2 b = __floats2half2_rn(v.z, v.w);
    g_dx[i] = make_uint2(*(uint32_t*)&a, *(uint32_t*)&b);
}

// ---------------- CSR gather: fp16 state -> fp16 aggr ----------------
__global__ __launch_bounds__(256) void gather_kernel(const uint2* __restrict__ st,
                                                     uint2* __restrict__ ag) {
    int w    = (blockIdx.x * blockDim.x + threadIdx.x) >> 5;
    int lane = threadIdx.x & 31;
    if (w >= NN) return;
    int beg = g_rowptr[w], end = g_rowptr[w + 1];
    float4 acc = make_float4(0.f, 0.f, 0.f, 0.f);
    int p = beg;
    for (; p + 1 < end; p += 2) {
        int s0 = g_col[p], s1 = g_col[p + 1];
        uint2 v0 = __ldg(&st[(size_t)s0 * 32 + lane]);
        uint2 v1 = __ldg(&st[(size_t)s1 * 32 + lane]);
        float2 a0 = __half22float2(*(const __half2*)&v0.x);
        float2 b0 = __half22float2(*(const __half2*)&v0.y);
        float2 a1 = __half22float2(*(const __half2*)&v1.x);
        float2 b1 = __half22float2(*(const __half2*)&v1.y);
        acc.x += a0.x + a1.x; acc.y += a0.y + a1.y;
        acc.z += b0.x + b1.x; acc.w += b0.y + b1.y;
    }
    if (p < end) {
        int s0 = g_col[p];
        uint2 v0 = __ldg(&st[(size_t)s0 * 32 + lane]);
        float2 a0 = __half22float2(*(const __half2*)&v0.x);
        float2 b0 = __half22float2(*(const __half2*)&v0.y);
        acc.x += a0.x; acc.y += a0.y; acc.z += b0.x; acc.w += b0.y;
    }
    __half2 h0v = __floats2half2_rn(acc.x, acc.y);
    __half2 h1v = __floats2half2_rn(acc.z, acc.w);
    ag[(size_t)w * 32 + lane] = make_uint2(*(uint32_t*)&h0v, *(uint32_t*)&h1v);
}

// ---------------- tensor GEMM: C = post( A @ W^T [+ XP] ) ----------------
// A fp16 single [NN][128]; W fp16 hi/lo. 2-term: A*Whi + A*Wlo, fp32 acc.
// MODE 0: write xp fp32 + tanh -> dst fp16 (no ADD)
// MODE 1: ADD xp, tanh, write fp16
// MODE 3: ADD xp, tanh, write fp32
template <int MODE>
__global__ __launch_bounds__(256, 2)
void gemm_k(const uint4* __restrict__ Ah, const uint4* __restrict__ W4,
            const float* __restrict__ XP, float* __restrict__ xpOut,
            void* __restrict__ dstOut) {
    extern __shared__ char smc[];
    const uint32_t sb = smem_u32(smc);
    const int tid = threadIdx.x, wid = tid >> 5, lane = tid & 31;
    const int qg = lane & 3, rg = lane >> 2;
    const int nq = wid & 1, mg = wid >> 1;
    const int rowBase = blockIdx.x * 128;

    // prologue: cp.async W (4352 x 16B) + A chunk 0 (1024 x 16B)
#pragma unroll
    for (int i = 0; i < 17; i++) {
        int f = tid + i * 256;
        cpa16(sb + f * 16, W4 + f);
    }
#pragma unroll
    for (int i = 0; i < 4; i++) {
        int f = tid + i * 256;
        int r = f >> 3, u = f & 7;
        int srow = rowBase + r; if (srow >= NN) srow = 0;
        cpa16(sb + A_B + r * 144 + u * 16, Ah + (size_t)srow * 16 + u);
    }
    cpa_commit();

    const int lrow = lane & 15, khalf = lane >> 4;
    const uint32_t aoff0 = (mg * 16 + lrow) * 144 + khalf * 16;
    const uint32_t aoff1 = ((mg + 4) * 16 + lrow) * 144 + khalf * 16;
    const int og = lane >> 3, lr = lane & 7;
    const uint32_t boff = (uint32_t)(nq * 64 + (og >> 1) * 8 + lr) * 272 + (og & 1) * 16;

    float acc[2][8][4];
#pragma unroll
    for (int m = 0; m < 2; m++)
#pragma unroll
        for (int nt = 0; nt < 8; nt++)
#pragma unroll
            for (int q = 0; q < 4; q++) acc[m][nt][q] = 0.f;

    for (int c = 0; c < 2; c++) {
        cpa_wait0();
        __syncthreads();
#pragma unroll
        for (int ks = 0; ks < 4; ks++) {
            const uint32_t kb = ks * 32;
            uint32_t a0[4], a1[4];
            ldsm4(a0, sb + A_B + aoff0 + kb);
            ldsm4(a1, sb + A_B + aoff1 + kb);
            const uint32_t kwb = c * 128 + kb;
#pragma unroll
            for (int p = 0; p < 4; p++) {
                uint32_t bh[4], bl[4];
                ldsm4(bh, sb + WHI_B + boff + p * 4352 + kwb);
                ldsm4(bl, sb + WLO_B + boff + p * 4352 + kwb);
                mma16816(acc[0][2 * p],     a0, &bh[0]);
                mma16816(acc[0][2 * p],     a0, &bl[0]);
                mma16816(acc[0][2 * p + 1], a0, &bh[2]);
                mma16816(acc[0][2 * p + 1], a0, &bl[2]);
                mma16816(acc[1][2 * p],     a1, &bh[0]);
                mma16816(acc[1][2 * p],     a1, &bl[0]);
                mma16816(acc[1][2 * p + 1], a1, &bh[2]);
                mma16816(acc[1][2 * p + 1], a1, &bl[2]);
            }
        }
        if (c == 0) {
            __syncthreads();
#pragma unroll
            for (int i = 0; i < 4; i++) {
                int f = tid + i * 256;
                int r = f >> 3, u = f & 7;
                int srow = rowBase + r; if (srow >= NN) srow = 0;
                cpa16(sb + A_B + r * 144 + u * 16, Ah + (size_t)srow * 16 + 8 + u);
            }
            cpa_commit();
        }
    }

    // epilogue
#pragma unroll
    for (int m = 0; m < 2; m++) {
        const int t = mg + m * 4;
#pragma unroll
        for (int half = 0; half < 2; half++) {
            const int row = rowBase + t * 16 + rg + half * 8;
            if (row >= NN) continue;
#pragma unroll
            for (int nt = 0; nt < 8; nt++) {
                const int col = nq * 64 + nt * 8 + qg * 2;
                float ox = acc[m][nt][half * 2], oy = acc[m][nt][half * 2 + 1];
                if (MODE != 0) {
                    float2 xv = *(const float2*)(XP + (size_t)row * H + col);
                    ox += xv.x; oy += xv.y;
                }
                if (MODE == 0) {
                    *(float2*)(xpOut + (size_t)row * H + col) = make_float2(ox, oy);
                    __half2 pp = __floats2half2_rn(tanhf(ox), tanhf(oy));
                    *(__half2*)((__half*)dstOut + (size_t)row * H + col) = pp;
                } else if (MODE == 1) {
                    __half2 pp = __floats2half2_rn(tanhf(ox), tanhf(oy));
                    *(__half2*)((__half*)dstOut + (size_t)row * H + col) = pp;
                } else {
                    *(float2*)((float*)dstOut + (size_t)row * H + col) =
                        make_float2(tanhf(ox), tanhf(oy));
                }
            }
        }
    }
}

// ---------------- launcher ----------------
extern "C" void kernel_launch(void* const* d_in, const int* in_sizes, int n_in,
                              void* d_out, int out_size) {
    const void*  ei     = d_in[0];
    const float* x      = (const float*)d_in[1];
    const float* w_in0  = (const float*)d_in[2];
    const float* w_rec0 = (const float*)d_in[3];
    const float* w_in1  = (const float*)d_in[4];
    const float* w_rec1 = (const float*)d_in[5];
    float*       out    = (float*)d_out;

    void *pxp, *ps0, *ps1, *pag, *pdx, *pdh, *pwp;
    cudaGetSymbolAddress(&pxp, g_xp);
    cudaGetSymbolAddress(&ps0, g_st0);
    cudaGetSymbolAddress(&ps1, g_st1);
    cudaGetSymbolAddress(&pag, g_ag);
    cudaGetSymbolAddress(&pdx, g_dx);
    cudaGetSymbolAddress(&pdh, g_dh);
    cudaGetSymbolAddress(&pwp, g_wp);
    float* xp    = (float*)pxp;
    uint2* st[2] = { (uint2*)ps0, (uint2*)ps1 };
    uint2* ag    = (uint2*)pag;
    uint2* dx    = (uint2*)pdx;
    uint2* dh    = (uint2*)pdh;
    uint4* wp    = (uint4*)pwp;

    cudaFuncSetAttribute(gemm_k<0>, cudaFuncAttributeMaxDynamicSharedMemorySize, SMEM_GEMM);
    cudaFuncSetAttribute(gemm_k<1>, cudaFuncAttributeMaxDynamicSharedMemorySize, SMEM_GEMM);
    cudaFuncSetAttribute(gemm_k<3>, cudaFuncAttributeMaxDynamicSharedMemorySize, SMEM_GEMM);

    const int GB = (NN + 127) / 128;   // 313

    // ---- CSR build ----
    zero_detect_kernel<<<(NN + 255) / 256, 256>>>((const int*)ei);
    hist_kernel<<<(NE + 255) / 256, 256>>>(ei);
    bsum_kernel<<<GB, 128>>>();
    bscan_kernel<<<1, 512>>>();
    rowptr_kernel<<<GB, 128>>>();
    scatter_kernel<<<(NE + 255) / 256, 256>>>(ei);

    // ---- weight prep + x split ----
    prep_w_all<<<256, 256>>>(w_in0, w_rec0, w_in1, w_rec1);
    split_x_kernel<<<(NN * 32 + 255) / 256, 256>>>((const float4*)x);

    // ---- layer 0 ----
    gemm_k<0><<<GB, 256, SMEM_GEMM>>>((const uint4*)dx, wp + 0 * 4352, nullptr, xp, st[0]);
    for (int it = 0; it < ITERS; it++) {
        gather_kernel<<<(NN * 32 + 255) / 256, 256>>>(st[it & 1], ag);
        void* dst = (it < ITERS - 1) ? (void*)st[(it + 1) & 1] : (void*)dh;
        gemm_k<1><<<GB, 256, SMEM_GEMM>>>((const uint4*)ag, wp + 1 * 4352, xp, nullptr, dst);
    }

    // ---- layer 1 ----
    gemm_k<0><<<GB, 256, SMEM_GEMM>>>((const uint4*)dh, wp + 2 * 4352, nullptr, xp, st[0]);
    for (int it = 0; it < ITERS; it++) {
        gather_kernel<<<(NN * 32 + 255) / 256, 256>>>(st[it & 1], ag);
        if (it < ITERS - 1)
            gemm_k<1><<<GB, 256, SMEM_GEMM>>>((const uint4*)ag, wp + 3 * 4352, xp, nullptr, st[(it + 1) & 1]);
        else
            gemm_k<3><<<GB, 256, SMEM_GEMM>>>((const uint4*)ag, wp + 3 * 4352, xp, nullptr, out);
    }
}